// round 2
// baseline (speedup 1.0000x reference)
#include <cuda_runtime.h>
#include <math_constants.h>

#define H 1536
#define W 1536
#define HW (H*W)
#define TS 64            // output tile
#define RAD 5            // KS/2
#define TMPW 74          // TS + 2*RAD
#define TMPSTR 76        // padded row stride (16B-aligned float4 rows)
#define DD 6             // max |offset|
#define AW 86            // TMPW + 2*DD
#define ASTR 88          // float4 row stride for A tile
#define NPOS (TMPW*TMPW) // 5476
#define NTH 1024
#define KPOS 6
#define REM (NPOS - (KPOS-1)*NTH)   // 356
#define BPLANE (TMPW*TMPSTR)        // 5624 floats

// smem: sA float4[AW*ASTR] | sB float[3*BPLANE] | sTmp float[BPLANE]
#define SMEM_BYTES (AW*ASTR*16 + 3*BPLANE*4 + BPLANE*4)   // 211072

__device__ float g_res[HW];

__global__ __launch_bounds__(NTH, 1)
void dewarp_main(const float* __restrict__ A, const float* __restrict__ B) {
    extern __shared__ unsigned char smem_raw[];
    float4* sA  = (float4*)smem_raw;
    float*  sB  = (float*)(smem_raw + AW*ASTR*16);
    float*  sTmp = sB + 3*BPLANE;

    const int tid = threadIdx.x;
    const int by0 = blockIdx.y * TS, bx0 = blockIdx.x * TS;

    // ---- Load zero-padded A region as float4 (3 channels + pad) ----
    for (int i = tid; i < AW*AW; i += NTH) {
        int ay = i / AW, ax = i - ay*AW;
        int gy = by0 - (RAD+DD) + ay;
        int gx = bx0 - (RAD+DD) + ax;
        float4 v = make_float4(0.f, 0.f, 0.f, 0.f);
        if ((unsigned)gy < (unsigned)H && (unsigned)gx < (unsigned)W) {
            int g = gy*W + gx;
            v.x = A[g];
            v.y = A[g + HW];
            v.z = A[g + 2*HW];
        }
        sA[ay*ASTR + ax] = v;
    }

    // ---- Load B tile into smem (3 planes, stride TMPSTR), zero-pad OOB ----
    for (int i = tid; i < NPOS; i += NTH) {
        int ty = i / TMPW, tx = i - ty*TMPW;
        int gy = by0 - RAD + ty;
        int gx = bx0 - RAD + tx;
        float v0 = 0.f, v1 = 0.f, v2 = 0.f;
        if ((unsigned)gy < (unsigned)H && (unsigned)gx < (unsigned)W) {
            int g = gy*W + gx;
            v0 = B[g]; v1 = B[g + HW]; v2 = B[g + 2*HW];
        }
        int s = ty*TMPSTR + tx;
        sB[s] = v0; sB[s + BPLANE] = v1; sB[s + 2*BPLANE] = v2;
    }

    // ---- per-thread phase-1 position metadata ----
    int  abase[KPOS], tbase[KPOS];
    bool vld[KPOS];
    #pragma unroll
    for (int k = 0; k < KPOS; k++) {
        int pos = tid + k*NTH;
        int ty, tx;
        if (pos < NPOS) { ty = pos / TMPW; tx = pos - ty*TMPW; }
        else            { ty = 0; tx = 0; }
        int gy = by0 - RAD + ty;
        int gx = bx0 - RAD + tx;
        vld[k]   = (pos < NPOS) && ((unsigned)gy < (unsigned)H) && ((unsigned)gx < (unsigned)W);
        abase[k] = (ty + DD)*ASTR + (tx + DD);
        tbase[k] = ty*TMPSTR + tx;
    }

    // phase-2 ownership: 4 consecutive x in one output row
    const int yo = tid >> 4;
    const int xs = (tid & 15) << 2;

    float wm0 = CUDART_INF_F, wm1 = CUDART_INF_F, wm2 = CUDART_INF_F, wm3 = CUDART_INF_F;
    float r0 = 0.f, r1 = 0.f, r2 = 0.f, r3 = 0.f;

    __syncthreads();

    for (int o = 0; o < 169; ++o) {
        const int od  = o / 13;
        const int dxo = od - DD;           // dx outer (matches reference loop order)
        const int dyo = (o - od*13) - DD;  // dy inner
        const int aoff = dyo*ASTR + dxo;

        // ---- phase 1: tmp = sqrt((d0^2 + d1^2) + d2^2), exact .rn ops ----
        #pragma unroll
        for (int k = 0; k < KPOS; k++) {
            if (k < KPOS-1 || tid < REM) {
                float4 a = sA[abase[k] + aoff];
                int s = tbase[k];
                float d0 = __fsub_rn(a.x, sB[s]);
                float d1 = __fsub_rn(a.y, sB[s + BPLANE]);
                float d2 = __fsub_rn(a.z, sB[s + 2*BPLANE]);
                float q  = __fadd_rn(__fadd_rn(__fmul_rn(d0,d0), __fmul_rn(d1,d1)),
                                     __fmul_rn(d2,d2));
                float t = __fsqrt_rn(q);
                sTmp[s] = vld[k] ? t : 0.f;
            }
        }
        __syncthreads();

        // ---- phase 2: exact sequential 11x11 window sums (row-major fold),
        //      bit-matching XLA's naive reduce_window emission ----
        {
            float a0 = 0.f, a1 = 0.f, a2 = 0.f, a3 = 0.f;
            const float* rowp = sTmp + yo*TMPSTR + xs;
            #pragma unroll
            for (int rr = 0; rr < 11; rr++) {
                const float* p = rowp + rr*TMPSTR;
                float4 q0 = *(const float4*)p;
                float4 q1 = *(const float4*)(p + 4);
                float4 q2 = *(const float4*)(p + 8);
                float2 q3 = *(const float2*)(p + 12);
                float v[14] = {q0.x,q0.y,q0.z,q0.w, q1.x,q1.y,q1.z,q1.w,
                               q2.x,q2.y,q2.z,q2.w, q3.x,q3.y};
                #pragma unroll
                for (int k = 0; k < 11; k++) {
                    a0 = __fadd_rn(a0, v[k]);
                    a1 = __fadd_rn(a1, v[k+1]);
                    a2 = __fadd_rn(a2, v[k+2]);
                    a3 = __fadd_rn(a3, v[k+3]);
                }
            }
            // w = s / 121 with IEEE division, exactly as the reference
            float w0 = __fdiv_rn(a0, 121.0f);
            float w1 = __fdiv_rn(a1, 121.0f);
            float w2 = __fdiv_rn(a2, 121.0f);
            float w3 = __fdiv_rn(a3, 121.0f);

            const int cb = (yo + RAD)*TMPSTR + (xs + RAD);
            float t0 = sTmp[cb + 0];
            float t1 = sTmp[cb + 1];
            float t2 = sTmp[cb + 2];
            float t3 = sTmp[cb + 3];

            // ties go to the newer candidate (w <= running)
            if (w0 <= wm0) { wm0 = w0; r0 = t0; }
            if (w1 <= wm1) { wm1 = w1; r1 = t1; }
            if (w2 <= wm2) { wm2 = w2; r2 = t2; }
            if (w3 <= wm3) { wm3 = w3; r3 = t3; }
        }
        __syncthreads();  // sTmp consumed before next offset overwrites
    }

    float4 out4 = make_float4(r0, r1, r2, r3);
    *(float4*)(g_res + (by0 + yo)*W + (bx0 + xs)) = out4;
}

// ---- final 3x3 min-pool (inf pad == clamped window) ----
__global__ void minpool3(float* __restrict__ out) {
    int x = blockIdx.x*blockDim.x + threadIdx.x;
    int y = blockIdx.y*blockDim.y + threadIdx.y;
    if (x >= W || y >= H) return;
    float m = CUDART_INF_F;
    #pragma unroll
    for (int dy = -1; dy <= 1; dy++) {
        int yy = y + dy;
        if ((unsigned)yy >= (unsigned)H) continue;
        const float* row = g_res + yy*W;
        #pragma unroll
        for (int dx = -1; dx <= 1; dx++) {
            int xx = x + dx;
            if ((unsigned)xx < (unsigned)W) m = fminf(m, row[xx]);
        }
    }
    out[y*W + x] = m;
}

extern "C" void kernel_launch(void* const* d_in, const int* in_sizes, int n_in,
                              void* d_out, int out_size) {
    const float* A = (const float*)d_in[0];
    const float* B = (const float*)d_in[1];
    float* out = (float*)d_out;

    cudaFuncSetAttribute(dewarp_main,
                         cudaFuncAttributeMaxDynamicSharedMemorySize, SMEM_BYTES);

    dim3 grid(W/TS, H/TS);
    dewarp_main<<<grid, NTH, SMEM_BYTES>>>(A, B);

    dim3 b2(32, 8);
    dim3 g2(W/32, H/8);
    minpool3<<<g2, b2>>>(out);
}

// round 3
// speedup vs baseline: 1.9095x; 1.9095x over previous
#include <cuda_runtime.h>
#include <math_constants.h>

#define H 1536
#define W 1536
#define HW (H*W)
#define TS 64            // output tile
#define RAD 5            // KS/2
#define TMPW 74          // TS + 2*RAD
#define TMPSTR 76        // padded row stride
#define DD 6             // max |offset|
#define AW 86            // TMPW + 2*DD
#define ASTR 88          // float4 row stride for A tile
#define NPOS (TMPW*TMPW) // 5476
#define NTH 1024
#define KPOS 6
#define REM (NPOS - (KPOS-1)*NTH)   // 356
#define BPLANE (TMPW*TMPSTR)        // 5624 floats
#define VSTR 76

// smem: sA float4[AW*ASTR] | sB float[3*BPLANE] | sTmp float[BPLANE] | sV float[64*VSTR]
#define SMEM_BYTES (AW*ASTR*16 + 3*BPLANE*4 + BPLANE*4 + TS*VSTR*4)  // 230528

__device__ float g_res[HW];

__global__ __launch_bounds__(NTH, 1)
void dewarp_main(const float* __restrict__ A, const float* __restrict__ B) {
    extern __shared__ unsigned char smem_raw[];
    float4* sA   = (float4*)smem_raw;
    float*  sB   = (float*)(smem_raw + AW*ASTR*16);
    float*  sTmp = sB + 3*BPLANE;
    float*  sV   = sTmp + BPLANE;

    const int tid = threadIdx.x;
    const int by0 = blockIdx.y * TS, bx0 = blockIdx.x * TS;

    // ---- Load zero-padded A region as float4 (3 channels + pad) ----
    for (int i = tid; i < AW*AW; i += NTH) {
        int ay = i / AW, ax = i - ay*AW;
        int gy = by0 - (RAD+DD) + ay;
        int gx = bx0 - (RAD+DD) + ax;
        float4 v = make_float4(0.f, 0.f, 0.f, 0.f);
        if ((unsigned)gy < (unsigned)H && (unsigned)gx < (unsigned)W) {
            int g = gy*W + gx;
            v.x = A[g];
            v.y = A[g + HW];
            v.z = A[g + 2*HW];
        }
        sA[ay*ASTR + ax] = v;
    }

    // ---- Load B tile into smem (3 planes, stride TMPSTR), zero-pad OOB ----
    for (int i = tid; i < NPOS; i += NTH) {
        int ty = i / TMPW, tx = i - ty*TMPW;
        int gy = by0 - RAD + ty;
        int gx = bx0 - RAD + tx;
        float v0 = 0.f, v1 = 0.f, v2 = 0.f;
        if ((unsigned)gy < (unsigned)H && (unsigned)gx < (unsigned)W) {
            int g = gy*W + gx;
            v0 = B[g]; v1 = B[g + HW]; v2 = B[g + 2*HW];
        }
        int s = ty*TMPSTR + tx;
        sB[s] = v0; sB[s + BPLANE] = v1; sB[s + 2*BPLANE] = v2;
    }

    // ---- per-thread phase-1 position metadata ----
    int  abase[KPOS], tbase[KPOS];
    bool vld[KPOS];
    #pragma unroll
    for (int k = 0; k < KPOS; k++) {
        int pos = tid + k*NTH;
        int ty, tx;
        if (pos < NPOS) { ty = pos / TMPW; tx = pos - ty*TMPW; }
        else            { ty = 0; tx = 0; }
        int gy = by0 - RAD + ty;
        int gx = bx0 - RAD + tx;
        vld[k]   = (pos < NPOS) && ((unsigned)gy < (unsigned)H) && ((unsigned)gx < (unsigned)W);
        abase[k] = (ty + DD)*ASTR + (tx + DD);
        tbase[k] = ty*TMPSTR + tx;
    }

    // vertical-sum ownership: 592 threads, one (col, 8-row segment) each
    const bool vact = (tid < TMPW*8);
    int vcy = 0, vtx = 0;
    if (vact) { vcy = tid / TMPW; vtx = tid - vcy*TMPW; }
    const int vy0 = vcy * 8;

    // horizontal ownership: 4 consecutive x in one output row
    const int yo = tid >> 4;
    const int xs = (tid & 15) << 2;

    float wm0 = CUDART_INF_F, wm1 = CUDART_INF_F, wm2 = CUDART_INF_F, wm3 = CUDART_INF_F;
    float r0 = 0.f, r1 = 0.f, r2 = 0.f, r3 = 0.f;

    __syncthreads();

    for (int o = 0; o < 169; ++o) {
        const int od  = o / 13;
        const int dxo = od - DD;           // dx outer (matches reference loop order)
        const int dyo = (o - od*13) - DD;  // dy inner
        const int aoff = dyo*ASTR + dxo;

        // ---- phase 1: tmp = sqrt((d0^2 + d1^2) + d2^2), exact .rn ops ----
        #pragma unroll
        for (int k = 0; k < KPOS; k++) {
            if (k < KPOS-1 || tid < REM) {
                float4 a = sA[abase[k] + aoff];
                int s = tbase[k];
                float d0 = __fsub_rn(a.x, sB[s]);
                float d1 = __fsub_rn(a.y, sB[s + BPLANE]);
                float d2 = __fsub_rn(a.z, sB[s + 2*BPLANE]);
                float q  = __fadd_rn(__fadd_rn(__fmul_rn(d0,d0), __fmul_rn(d1,d1)),
                                     __fmul_rn(d2,d2));
                float t = __fsqrt_rn(q);
                sTmp[s] = vld[k] ? t : 0.f;
            }
        }
        __syncthreads();

        // ---- phase 2a: fresh vertical 11-tap folds (no sliding/cancellation) ----
        if (vact) {
            const float* col = sTmp + vy0*TMPSTR + vtx;
            float v[18];
            #pragma unroll
            for (int j = 0; j < 18; j++) v[j] = col[j*TMPSTR];
            float* vo = sV + vy0*VSTR + vtx;
            #pragma unroll
            for (int j = 0; j < 8; j++) {
                float s = v[j];
                #pragma unroll
                for (int k = 1; k < 11; k++) s = __fadd_rn(s, v[j + k]);
                vo[j*VSTR] = s;
            }
        }
        __syncthreads();

        // ---- phase 2b: fresh horizontal 11-tap folds + w = s/121 + argmin ----
        {
            const float* rowp = sV + yo*VSTR + xs;
            float4 q0 = *(const float4*)rowp;
            float4 q1 = *(const float4*)(rowp + 4);
            float4 q2 = *(const float4*)(rowp + 8);
            float2 q3 = *(const float2*)(rowp + 12);
            float v[14] = {q0.x,q0.y,q0.z,q0.w, q1.x,q1.y,q1.z,q1.w,
                           q2.x,q2.y,q2.z,q2.w, q3.x,q3.y};

            float a0 = v[0], a1 = v[1], a2 = v[2], a3 = v[3];
            #pragma unroll
            for (int k = 1; k < 11; k++) {
                a0 = __fadd_rn(a0, v[k]);
                a1 = __fadd_rn(a1, v[k+1]);
                a2 = __fadd_rn(a2, v[k+2]);
                a3 = __fadd_rn(a3, v[k+3]);
            }
            float w0 = __fdiv_rn(a0, 121.0f);
            float w1 = __fdiv_rn(a1, 121.0f);
            float w2 = __fdiv_rn(a2, 121.0f);
            float w3 = __fdiv_rn(a3, 121.0f);

            const int cb = (yo + RAD)*TMPSTR + (xs + RAD);
            float t0 = sTmp[cb + 0];
            float t1 = sTmp[cb + 1];
            float t2 = sTmp[cb + 2];
            float t3 = sTmp[cb + 3];

            // ties go to the newer candidate (w <= running)
            if (w0 <= wm0) { wm0 = w0; r0 = t0; }
            if (w1 <= wm1) { wm1 = w1; r1 = t1; }
            if (w2 <= wm2) { wm2 = w2; r2 = t2; }
            if (w3 <= wm3) { wm3 = w3; r3 = t3; }
        }
        __syncthreads();  // sTmp/sV consumed before next offset overwrites
    }

    float4 out4 = make_float4(r0, r1, r2, r3);
    *(float4*)(g_res + (by0 + yo)*W + (bx0 + xs)) = out4;
}

// ---- final 3x3 min-pool (inf pad == clamped window) ----
__global__ void minpool3(float* __restrict__ out) {
    int x = blockIdx.x*blockDim.x + threadIdx.x;
    int y = blockIdx.y*blockDim.y + threadIdx.y;
    if (x >= W || y >= H) return;
    float m = CUDART_INF_F;
    #pragma unroll
    for (int dy = -1; dy <= 1; dy++) {
        int yy = y + dy;
        if ((unsigned)yy >= (unsigned)H) continue;
        const float* row = g_res + yy*W;
        #pragma unroll
        for (int dx = -1; dx <= 1; dx++) {
            int xx = x + dx;
            if ((unsigned)xx < (unsigned)W) m = fminf(m, row[xx]);
        }
    }
    out[y*W + x] = m;
}

extern "C" void kernel_launch(void* const* d_in, const int* in_sizes, int n_in,
                              void* d_out, int out_size) {
    const float* A = (const float*)d_in[0];
    const float* B = (const float*)d_in[1];
    float* out = (float*)d_out;

    cudaFuncSetAttribute(dewarp_main,
                         cudaFuncAttributeMaxDynamicSharedMemorySize, SMEM_BYTES);

    dim3 grid(W/TS, H/TS);
    dewarp_main<<<grid, NTH, SMEM_BYTES>>>(A, B);

    dim3 b2(32, 8);
    dim3 g2(W/32, H/8);
    minpool3<<<g2, b2>>>(out);
}

// round 4
// speedup vs baseline: 2.4239x; 1.2693x over previous
#include <cuda_runtime.h>
#include <math_constants.h>

#define H 1536
#define W 1536
#define HW (H*W)
#define TS 64            // output tile
#define RAD 5            // KS/2
#define TMPW 74          // TS + 2*RAD
#define TMPSTR 76        // padded row stride
#define DD 6             // max |offset|
#define AW 86            // TMPW + 2*DD
#define ASTR 88          // float4 row stride for A tile
#define NPOS (TMPW*TMPW) // 5476
#define NTH 1024
#define KPOS 6
#define REM (NPOS - (KPOS-1)*NTH)   // 356
#define BPLANE (TMPW*TMPSTR)        // 5624 floats
#define VSTR 76

// smem: sA float4[AW*ASTR] | sB float[3*BPLANE] | sTmp float[BPLANE] | sV float[64*VSTR]
#define SMEM_BYTES (AW*ASTR*16 + 3*BPLANE*4 + BPLANE*4 + TS*VSTR*4)  // 230528

__device__ float g_res[HW];

__device__ __forceinline__ float sqrt_approx(float x) {
    float r;
    asm("sqrt.approx.f32 %0, %1;" : "=f"(r) : "f"(x));
    return r;
}

__global__ __launch_bounds__(NTH, 1)
void dewarp_main(const float* __restrict__ A, const float* __restrict__ B) {
    extern __shared__ unsigned char smem_raw[];
    float4* sA   = (float4*)smem_raw;
    float*  sB   = (float*)(smem_raw + AW*ASTR*16);
    float*  sTmp = sB + 3*BPLANE;
    float*  sV   = sTmp + BPLANE;

    const int tid = threadIdx.x;
    const int by0 = blockIdx.y * TS, bx0 = blockIdx.x * TS;

    // ---- Load zero-padded A region as float4 (3 channels + pad) ----
    for (int i = tid; i < AW*AW; i += NTH) {
        int ay = i / AW, ax = i - ay*AW;
        int gy = by0 - (RAD+DD) + ay;
        int gx = bx0 - (RAD+DD) + ax;
        float4 v = make_float4(0.f, 0.f, 0.f, 0.f);
        if ((unsigned)gy < (unsigned)H && (unsigned)gx < (unsigned)W) {
            int g = gy*W + gx;
            v.x = A[g];
            v.y = A[g + HW];
            v.z = A[g + 2*HW];
        }
        sA[ay*ASTR + ax] = v;
    }

    // ---- Load B tile into smem (3 planes, stride TMPSTR), zero-pad OOB ----
    for (int i = tid; i < NPOS; i += NTH) {
        int ty = i / TMPW, tx = i - ty*TMPW;
        int gy = by0 - RAD + ty;
        int gx = bx0 - RAD + tx;
        float v0 = 0.f, v1 = 0.f, v2 = 0.f;
        if ((unsigned)gy < (unsigned)H && (unsigned)gx < (unsigned)W) {
            int g = gy*W + gx;
            v0 = B[g]; v1 = B[g + HW]; v2 = B[g + 2*HW];
        }
        int s = ty*TMPSTR + tx;
        sB[s] = v0; sB[s + BPLANE] = v1; sB[s + 2*BPLANE] = v2;
    }

    // ---- per-thread phase-1 position metadata ----
    int  abase[KPOS], tbase[KPOS];
    bool vld[KPOS];
    #pragma unroll
    for (int k = 0; k < KPOS; k++) {
        int pos = tid + k*NTH;
        int ty, tx;
        if (pos < NPOS) { ty = pos / TMPW; tx = pos - ty*TMPW; }
        else            { ty = 0; tx = 0; }
        int gy = by0 - RAD + ty;
        int gx = bx0 - RAD + tx;
        vld[k]   = (pos < NPOS) && ((unsigned)gy < (unsigned)H) && ((unsigned)gx < (unsigned)W);
        abase[k] = (ty + DD)*ASTR + (tx + DD);
        tbase[k] = ty*TMPSTR + tx;
    }

    // vertical-sum ownership: 592 threads, one (col, 8-row segment) each
    const bool vact = (tid < TMPW*8);
    int vcy = 0, vtx = 0;
    if (vact) { vcy = tid / TMPW; vtx = tid - vcy*TMPW; }
    const int vy0 = vcy * 8;

    // horizontal ownership: 4 consecutive x in one output row
    const int yo = tid >> 4;
    const int xs = (tid & 15) << 2;

    float wm0 = CUDART_INF_F, wm1 = CUDART_INF_F, wm2 = CUDART_INF_F, wm3 = CUDART_INF_F;
    float r0 = 0.f, r1 = 0.f, r2 = 0.f, r3 = 0.f;

    __syncthreads();

    for (int o = 0; o < 169; ++o) {
        const int od  = o / 13;
        const int dxo = od - DD;           // dx outer (matches reference loop order)
        const int dyo = (o - od*13) - DD;  // dy inner
        const int aoff = dyo*ASTR + dxo;

        // ---- phase 1: tmp = sqrt((d0^2 + d1^2) + d2^2) ----
        #pragma unroll
        for (int k = 0; k < KPOS; k++) {
            if (k < KPOS-1 || tid < REM) {
                float4 a = sA[abase[k] + aoff];
                int s = tbase[k];
                float d0 = __fsub_rn(a.x, sB[s]);
                float d1 = __fsub_rn(a.y, sB[s + BPLANE]);
                float d2 = __fsub_rn(a.z, sB[s + 2*BPLANE]);
                float q  = __fadd_rn(__fadd_rn(__fmul_rn(d0,d0), __fmul_rn(d1,d1)),
                                     __fmul_rn(d2,d2));
                float t = sqrt_approx(q);
                sTmp[s] = vld[k] ? t : 0.f;
            }
        }
        __syncthreads();

        // ---- phase 2a: vertical 11-tap folds, shared-subtree (fresh, no sliding) ----
        if (vact) {
            const float* col = sTmp + vy0*TMPSTR + vtx;
            float v[18];
            #pragma unroll
            for (int j = 0; j < 18; j++) v[j] = col[j*TMPSTR];

            // core = v7+v8+v9+v10
            float core = __fadd_rn(__fadd_rn(v[7], v[8]), __fadd_rn(v[9], v[10]));
            // down-prefixes a_j = v[j]+...+v[6]
            float a6 = v[6];
            float a5 = __fadd_rn(v[5], a6);
            float a4 = __fadd_rn(v[4], a5);
            float a3 = __fadd_rn(v[3], a4);
            float a2 = __fadd_rn(v[2], a3);
            float a1 = __fadd_rn(v[1], a2);
            float a0 = __fadd_rn(v[0], a1);
            // up-prefixes b_i = v[11]+...+v[i]
            float b11 = v[11];
            float b12 = __fadd_rn(b11, v[12]);
            float b13 = __fadd_rn(b12, v[13]);
            float b14 = __fadd_rn(b13, v[14]);
            float b15 = __fadd_rn(b14, v[15]);
            float b16 = __fadd_rn(b15, v[16]);
            float b17 = __fadd_rn(b16, v[17]);

            float* vo = sV + vy0*VSTR + vtx;
            vo[0*VSTR] = __fadd_rn(a0, core);
            vo[1*VSTR] = __fadd_rn(__fadd_rn(a1, core), b11);
            vo[2*VSTR] = __fadd_rn(__fadd_rn(a2, core), b12);
            vo[3*VSTR] = __fadd_rn(__fadd_rn(a3, core), b13);
            vo[4*VSTR] = __fadd_rn(__fadd_rn(a4, core), b14);
            vo[5*VSTR] = __fadd_rn(__fadd_rn(a5, core), b15);
            vo[6*VSTR] = __fadd_rn(__fadd_rn(a6, core), b16);
            vo[7*VSTR] = __fadd_rn(core, b17);
        }
        __syncthreads();

        // ---- phase 2b: horizontal 11-tap folds (shared subtree) + argmin on s ----
        {
            const float* rowp = sV + yo*VSTR + xs;
            float4 q0 = *(const float4*)rowp;
            float4 q1 = *(const float4*)(rowp + 4);
            float4 q2 = *(const float4*)(rowp + 8);
            float2 q3 = *(const float2*)(rowp + 12);
            float v0 = q0.x, v1 = q0.y, v2  = q0.z, v3  = q0.w;
            float v4 = q1.x, v5 = q1.y, v6  = q1.z, v7  = q1.w;
            float v8 = q2.x, v9 = q2.y, v10 = q2.z, v11 = q2.w;
            float v12 = q3.x, v13 = q3.y;

            // core = v3..v10 (7 adds)
            float core = __fadd_rn(
                __fadd_rn(__fadd_rn(v3, v4), __fadd_rn(v5, v6)),
                __fadd_rn(__fadd_rn(v7, v8), __fadd_rn(v9, v10)));
            float a2 = v2;
            float a1 = __fadd_rn(v1, a2);
            float a0 = __fadd_rn(v0, a1);
            float b11 = v11;
            float b12 = __fadd_rn(b11, v12);
            float b13 = __fadd_rn(b12, v13);

            float s0 = __fadd_rn(a0, core);
            float s1 = __fadd_rn(__fadd_rn(a1, core), b11);
            float s2 = __fadd_rn(__fadd_rn(a2, core), b12);
            float s3 = __fadd_rn(core, b13);

            const int cb = (yo + RAD)*TMPSTR + (xs + RAD);
            float t0 = sTmp[cb + 0];
            float t1 = sTmp[cb + 1];
            float t2 = sTmp[cb + 2];
            float t3 = sTmp[cb + 3];

            // argmin over s (== argmin over w = s/121); ties -> newer candidate
            if (s0 <= wm0) { wm0 = s0; r0 = t0; }
            if (s1 <= wm1) { wm1 = s1; r1 = t1; }
            if (s2 <= wm2) { wm2 = s2; r2 = t2; }
            if (s3 <= wm3) { wm3 = s3; r3 = t3; }
        }
        __syncthreads();  // sTmp/sV consumed before next offset overwrites
    }

    float4 out4 = make_float4(r0, r1, r2, r3);
    *(float4*)(g_res + (by0 + yo)*W + (bx0 + xs)) = out4;
}

// ---- final 3x3 min-pool (inf pad == clamped window) ----
__global__ void minpool3(float* __restrict__ out) {
    int x = blockIdx.x*blockDim.x + threadIdx.x;
    int y = blockIdx.y*blockDim.y + threadIdx.y;
    if (x >= W || y >= H) return;
    float m = CUDART_INF_F;
    #pragma unroll
    for (int dy = -1; dy <= 1; dy++) {
        int yy = y + dy;
        if ((unsigned)yy >= (unsigned)H) continue;
        const float* row = g_res + yy*W;
        #pragma unroll
        for (int dx = -1; dx <= 1; dx++) {
            int xx = x + dx;
            if ((unsigned)xx < (unsigned)W) m = fminf(m, row[xx]);
        }
    }
    out[y*W + x] = m;
}

extern "C" void kernel_launch(void* const* d_in, const int* in_sizes, int n_in,
                              void* d_out, int out_size) {
    const float* A = (const float*)d_in[0];
    const float* B = (const float*)d_in[1];
    float* out = (float*)d_out;

    cudaFuncSetAttribute(dewarp_main,
                         cudaFuncAttributeMaxDynamicSharedMemorySize, SMEM_BYTES);

    dim3 grid(W/TS, H/TS);
    dewarp_main<<<grid, NTH, SMEM_BYTES>>>(A, B);

    dim3 b2(32, 8);
    dim3 g2(W/32, H/8);
    minpool3<<<g2, b2>>>(out);
}

// round 5
// speedup vs baseline: 2.7291x; 1.1260x over previous
#include <cuda_runtime.h>
#include <math_constants.h>

#define H 1536
#define W 1536
#define HW (H*W)
#define TS 64            // output tile
#define RAD 5            // KS/2
#define TMPW 74          // TS + 2*RAD
#define TMPSTR 76        // padded row stride
#define DD 6             // max |offset|
#define AW 86            // TMPW + 2*DD
#define ASTR 88          // float4 row stride for A tile
#define NPOS (TMPW*TMPW) // 5476
#define NTH 1024
#define KPOS 6
#define REM (NPOS - (KPOS-1)*NTH)   // 356
#define BPLANE (TMPW*TMPSTR)        // 5624 floats
#define VSTR 76
#define SVPLANE (TS*VSTR)           // 4864 floats

// smem: sA float4[AW*ASTR] | sTmp[2*BPLANE] | sV[2*SVPLANE]
#define SMEM_BYTES (AW*ASTR*16 + 2*BPLANE*4 + 2*SVPLANE*4)  // 204992

__device__ float g_res[HW];

__device__ __forceinline__ float sqrt_approx(float x) {
    float r;
    asm("sqrt.approx.f32 %0, %1;" : "=f"(r) : "f"(x));
    return r;
}

__global__ __launch_bounds__(NTH, 1)
void dewarp_main(const float* __restrict__ A, const float* __restrict__ B) {
    extern __shared__ unsigned char smem_raw[];
    float4* sA    = (float4*)smem_raw;
    float*  sTmp0 = (float*)(smem_raw + AW*ASTR*16);
    float*  sV0   = sTmp0 + 2*BPLANE;

    const int tid = threadIdx.x;
    const int by0 = blockIdx.y * TS, bx0 = blockIdx.x * TS;

    // ---- Load zero-padded A region as float4 (3 channels + pad) ----
    for (int i = tid; i < AW*AW; i += NTH) {
        int ay = i / AW, ax = i - ay*AW;
        int gy = by0 - (RAD+DD) + ay;
        int gx = bx0 - (RAD+DD) + ax;
        float4 v = make_float4(0.f, 0.f, 0.f, 0.f);
        if ((unsigned)gy < (unsigned)H && (unsigned)gx < (unsigned)W) {
            int g = gy*W + gx;
            v.x = A[g];
            v.y = A[g + HW];
            v.z = A[g + 2*HW];
        }
        sA[ay*ASTR + ax] = v;
    }

    // ---- Pre-zero both tmp buffers (halo-invalid entries stay 0 forever) ----
    for (int i = tid; i < 2*BPLANE; i += NTH) sTmp0[i] = 0.f;

    // ---- B into registers + per-thread phase-1 metadata ----
    float b0[KPOS], b1[KPOS], b2[KPOS];
    int   abase[KPOS], tbase[KPOS];
    unsigned vldmask = 0;
    #pragma unroll
    for (int k = 0; k < KPOS; k++) {
        int pos = tid + k*NTH;
        int ty, tx;
        if (pos < NPOS) { ty = pos / TMPW; tx = pos - ty*TMPW; }
        else            { ty = 0; tx = 0; }
        int gy = by0 - RAD + ty;
        int gx = bx0 - RAD + tx;
        bool inb = (pos < NPOS) && ((unsigned)gy < (unsigned)H) && ((unsigned)gx < (unsigned)W);
        float v0 = 0.f, v1 = 0.f, v2 = 0.f;
        if (inb) {
            int g = gy*W + gx;
            v0 = B[g]; v1 = B[g + HW]; v2 = B[g + 2*HW];
        }
        b0[k] = v0; b1[k] = v1; b2[k] = v2;
        abase[k] = (ty + DD)*ASTR + (tx + DD);
        tbase[k] = ty*TMPSTR + tx;
        if (inb) vldmask |= (1u << k);
    }

    // vertical-sum ownership: 592 threads, one (col, 8-row segment) each
    const bool vact = (tid < TMPW*8);
    int vcy = 0, vtx = 0;
    if (vact) { vcy = tid / TMPW; vtx = tid - vcy*TMPW; }
    const int vy0 = vcy * 8;

    // horizontal ownership: 4 consecutive x in one output row
    const int yo = tid >> 4;
    const int xs = (tid & 15) << 2;

    float wm0 = CUDART_INF_F, wm1 = CUDART_INF_F, wm2 = CUDART_INF_F, wm3 = CUDART_INF_F;
    float r0 = 0.f, r1 = 0.f, r2 = 0.f, r3 = 0.f;

    __syncthreads();

    for (int o = 0; o < 169; ++o) {
        const int od  = o / 13;
        const int dxo = od - DD;           // dx outer (matches reference loop order)
        const int dyo = (o - od*13) - DD;  // dy inner
        const int aoff = dyo*ASTR + dxo;

        float* sTmp = sTmp0 + (o & 1)*BPLANE;
        float* sV   = sV0   + (o & 1)*SVPLANE;

        // ---- phase 1: tmp = sqrt((d0^2 + d1^2) + d2^2), predicated halo ----
        #pragma unroll
        for (int k = 0; k < KPOS; k++) {
            if ((k < KPOS-1 || tid < REM) && (vldmask >> k & 1u)) {
                float4 a = sA[abase[k] + aoff];
                float d0 = __fsub_rn(a.x, b0[k]);
                float d1 = __fsub_rn(a.y, b1[k]);
                float d2 = __fsub_rn(a.z, b2[k]);
                float q  = __fadd_rn(__fadd_rn(__fmul_rn(d0,d0), __fmul_rn(d1,d1)),
                                     __fmul_rn(d2,d2));
                sTmp[tbase[k]] = sqrt_approx(q);
            }
        }
        __syncthreads();

        // ---- phase 2a: vertical 11-tap folds, shared-subtree (fresh) ----
        if (vact) {
            const float* col = sTmp + vy0*TMPSTR + vtx;
            float v[18];
            #pragma unroll
            for (int j = 0; j < 18; j++) v[j] = col[j*TMPSTR];

            float core = __fadd_rn(__fadd_rn(v[7], v[8]), __fadd_rn(v[9], v[10]));
            float a6 = v[6];
            float a5 = __fadd_rn(v[5], a6);
            float a4 = __fadd_rn(v[4], a5);
            float a3 = __fadd_rn(v[3], a4);
            float a2 = __fadd_rn(v[2], a3);
            float a1 = __fadd_rn(v[1], a2);
            float a0 = __fadd_rn(v[0], a1);
            float b11 = v[11];
            float b12 = __fadd_rn(b11, v[12]);
            float b13 = __fadd_rn(b12, v[13]);
            float b14 = __fadd_rn(b13, v[14]);
            float b15 = __fadd_rn(b14, v[15]);
            float b16 = __fadd_rn(b15, v[16]);
            float b17 = __fadd_rn(b16, v[17]);

            float* vo = sV + vy0*VSTR + vtx;
            vo[0*VSTR] = __fadd_rn(a0, core);
            vo[1*VSTR] = __fadd_rn(__fadd_rn(a1, core), b11);
            vo[2*VSTR] = __fadd_rn(__fadd_rn(a2, core), b12);
            vo[3*VSTR] = __fadd_rn(__fadd_rn(a3, core), b13);
            vo[4*VSTR] = __fadd_rn(__fadd_rn(a4, core), b14);
            vo[5*VSTR] = __fadd_rn(__fadd_rn(a5, core), b15);
            vo[6*VSTR] = __fadd_rn(__fadd_rn(a6, core), b16);
            vo[7*VSTR] = __fadd_rn(core, b17);
        }
        __syncthreads();

        // ---- phase 2b: horizontal 11-tap folds (shared subtree) + argmin on s ----
        {
            const float* rowp = sV + yo*VSTR + xs;
            float4 q0 = *(const float4*)rowp;
            float4 q1 = *(const float4*)(rowp + 4);
            float4 q2 = *(const float4*)(rowp + 8);
            float2 q3 = *(const float2*)(rowp + 12);
            float v0 = q0.x, v1 = q0.y, v2  = q0.z, v3  = q0.w;
            float v4 = q1.x, v5 = q1.y, v6  = q1.z, v7  = q1.w;
            float v8 = q2.x, v9 = q2.y, v10 = q2.z, v11 = q2.w;
            float v12 = q3.x, v13 = q3.y;

            float core = __fadd_rn(
                __fadd_rn(__fadd_rn(v3, v4), __fadd_rn(v5, v6)),
                __fadd_rn(__fadd_rn(v7, v8), __fadd_rn(v9, v10)));
            float a2 = v2;
            float a1 = __fadd_rn(v1, a2);
            float a0 = __fadd_rn(v0, a1);
            float c11 = v11;
            float c12 = __fadd_rn(c11, v12);
            float c13 = __fadd_rn(c12, v13);

            float s0 = __fadd_rn(a0, core);
            float s1 = __fadd_rn(__fadd_rn(a1, core), c11);
            float s2 = __fadd_rn(__fadd_rn(a2, core), c12);
            float s3 = __fadd_rn(core, c13);

            const int cb = (yo + RAD)*TMPSTR + (xs + RAD);
            float t0 = sTmp[cb + 0];
            float t1 = sTmp[cb + 1];
            float t2 = sTmp[cb + 2];
            float t3 = sTmp[cb + 3];

            // argmin over s (== argmin over w = s/121); ties -> newer candidate
            if (s0 <= wm0) { wm0 = s0; r0 = t0; }
            if (s1 <= wm1) { wm1 = s1; r1 = t1; }
            if (s2 <= wm2) { wm2 = s2; r2 = t2; }
            if (s3 <= wm3) { wm3 = s3; r3 = t3; }
        }
        // no trailing sync: next phase-1 writes the other buffer; the sync
        // after it orders everything before this buffer is reused.
    }

    float4 out4 = make_float4(r0, r1, r2, r3);
    *(float4*)(g_res + (by0 + yo)*W + (bx0 + xs)) = out4;
}

// ---- final 3x3 min-pool (inf pad == clamped window) ----
__global__ void minpool3(float* __restrict__ out) {
    int x = blockIdx.x*blockDim.x + threadIdx.x;
    int y = blockIdx.y*blockDim.y + threadIdx.y;
    if (x >= W || y >= H) return;
    float m = CUDART_INF_F;
    #pragma unroll
    for (int dy = -1; dy <= 1; dy++) {
        int yy = y + dy;
        if ((unsigned)yy >= (unsigned)H) continue;
        const float* row = g_res + yy*W;
        #pragma unroll
        for (int dx = -1; dx <= 1; dx++) {
            int xx = x + dx;
            if ((unsigned)xx < (unsigned)W) m = fminf(m, row[xx]);
        }
    }
    out[y*W + x] = m;
}

extern "C" void kernel_launch(void* const* d_in, const int* in_sizes, int n_in,
                              void* d_out, int out_size) {
    const float* A = (const float*)d_in[0];
    const float* B = (const float*)d_in[1];
    float* out = (float*)d_out;

    cudaFuncSetAttribute(dewarp_main,
                         cudaFuncAttributeMaxDynamicSharedMemorySize, SMEM_BYTES);

    dim3 grid(W/TS, H/TS);
    dewarp_main<<<grid, NTH, SMEM_BYTES>>>(A, B);

    dim3 b2(32, 8);
    dim3 g2(W/32, H/8);
    minpool3<<<g2, b2>>>(out);
}